// round 9
// baseline (speedup 1.0000x reference)
#include <cuda_runtime.h>

#define H_   128
#define B_   64
#define T_   10
#define N_   64
#define D_   4
#define E_   4032
#define BE_  258048
#define BN_  4096
#define EPS_ 1e-5f
#define XS_  132   // smem transposed-tile stride (floats), 16B-aligned

// ---------------- device scratch ----------------
__device__ __align__(16) float g_t1[BN_ * H_];
__device__ __align__(16) float g_P[BN_ * H_];
__device__ __align__(16) float g_Q[BN_ * H_];
__device__ __align__(16) float g_skip[BE_ * H_];   // pre-BN mlp2 output
__device__ __align__(16) float g_h4[BE_ * H_];     // pre-BN mlp4 output
__device__ __align__(16) float g_agg[BN_ * H_];
__device__ __align__(16) float g_t3[BN_ * H_];
__device__ __align__(16) float g_R[BN_ * H_];
__device__ __align__(16) float g_S[BN_ * H_];
__device__ __align__(16) float g_psum[BN_ * H_];
__device__ __align__(16) float g_pss[BN_ * H_];
__device__ __align__(16) float g_ab[8][H_];        // a1,c1,a2,c2,a3,c3,a4,c4
__device__ __align__(16) float g_Wcp[H_ * H_];
__device__ __align__(16) float g_bias4[H_];
__device__ __align__(16) float g_fw[H_ * 2];
__device__ __align__(16) float g_fb[2];

// ---------------- helpers ----------------
__device__ __forceinline__ float eluf(float x) {
    return x > 0.f ? x : (__expf(x) - 1.f);
}

// packed dual fp32 FMA (Blackwell f32x2): c = a * (b,b) + c
__device__ __forceinline__ float2 ffma2s(float2 a, float bs, float2 c) {
    float2 b = make_float2(bs, bs);
    unsigned long long au = *reinterpret_cast<unsigned long long*>(&a);
    unsigned long long bu = *reinterpret_cast<unsigned long long*>(&b);
    unsigned long long cu = *reinterpret_cast<unsigned long long*>(&c);
    asm("fma.rn.f32x2 %0, %1, %2, %0;" : "+l"(cu) : "l"(au), "l"(bu));
    return *reinterpret_cast<float2*>(&cu);
}

__device__ __forceinline__ void decode_edge(int gr, int& b, int& s, int& r) {
    b = gr / E_;
    int e = gr - b * E_;
    s = e / 63;
    int jj = e - s * 63;
    r = jj + (jj >= s ? 1 : 0);
}

// one 32-k chunk; thread = 8m (4 float2 pairs) x 8n
__device__ __forceinline__ void gemm_chunk8(const float* sWc, const float* sXTc,
                                            int m0, int c0, float2 acc[4][8]) {
#pragma unroll 8
    for (int kk = 0; kk < 32; kk++) {
        float4 w0 = *(const float4*)(sWc + kk * 128 + c0);
        float4 w1 = *(const float4*)(sWc + kk * 128 + c0 + 4);
        float4 a0 = *(const float4*)(sXTc + kk * XS_ + m0);
        float4 a1 = *(const float4*)(sXTc + kk * XS_ + m0 + 4);
        float2 h[4];
        h[0] = make_float2(a0.x, a0.y); h[1] = make_float2(a0.z, a0.w);
        h[2] = make_float2(a1.x, a1.y); h[3] = make_float2(a1.z, a1.w);
        float wv[8] = {w0.x, w0.y, w0.z, w0.w, w1.x, w1.y, w1.z, w1.w};
#pragma unroll
        for (int mi = 0; mi < 4; mi++)
#pragma unroll
            for (int ni = 0; ni < 8; ni++)
                acc[mi][ni] = ffma2s(h[mi], wv[ni], acc[mi][ni]);
    }
}

__device__ __forceinline__ void load_chunk(float* dst, const float* __restrict__ W, int tid) {
    float4* d = (float4*)dst;
    const float4* s4 = (const float4*)W;
#pragma unroll
    for (int i = 0; i < 4; i++) d[tid + 256 * i] = s4[tid + 256 * i];
}

// full K=128 GEMM, double-buffered 32-k weight chunks (buffers at sW, sW+4096)
// precondition: sXT filled (no sync needed before; first sync covers it); ends synced.
__device__ __forceinline__ void gemm_streamW8(float* sW, const float* sXT,
                                              const float* __restrict__ W,
                                              int tid, int m0, int c0, float2 acc[4][8]) {
    load_chunk(sW, W, tid);
    __syncthreads();
    for (int ch = 0; ch < 4; ch++) {
        if (ch < 3) load_chunk(sW + ((ch + 1) & 1) * 4096, W + (ch + 1) * 4096, tid);
        gemm_chunk8(sW + (ch & 1) * 4096, sXT + ch * 32 * XS_, m0, c0, acc);
        __syncthreads();
    }
}

// ---------------- node-level kernels (4096 rows) ----------------
__global__ void k_mlp1(const float* __restrict__ inp, const float* __restrict__ w1,
                       const float* __restrict__ b1, const float* __restrict__ w2,
                       const float* __restrict__ b2) {
    extern __shared__ float sm[];
    float* sW = sm;
    float* sX = sm + 16384;
    float* sH = sX + 32 * 40;
    int tid = threadIdx.x;
    int row0 = blockIdx.x * 32;
    for (int i = tid; i < 40 * 128; i += 128) sW[i] = w1[i];
    for (int i = tid; i < 32 * 40; i += 128) {
        int rr = i / 40, k = i - rr * 40;
        int row = row0 + rr, b = row >> 6, n = row & 63;
        int t = k >> 2, d = k & 3;
        sX[i] = inp[((b * T_ + t) * N_ + n) * D_ + d];
    }
    __syncthreads();
    int j = tid;
    float bj = b1[j];
    for (int rr = 0; rr < 32; rr++) {
        float acc = bj;
        for (int k = 0; k < 40; k++) acc += sX[rr * 40 + k] * sW[k * 128 + j];
        sH[rr * 128 + j] = eluf(acc);
    }
    __syncthreads();
    for (int i = tid; i < 16384; i += 128) sW[i] = w2[i];
    __syncthreads();
    float bj2 = b2[j], cs = 0.f, css = 0.f;
    for (int rr = 0; rr < 32; rr++) {
        float acc = bj2;
#pragma unroll 8
        for (int k = 0; k < 128; k++) acc += sH[rr * 128 + k] * sW[k * 128 + j];
        float v = eluf(acc);
        g_t1[(row0 + rr) * H_ + j] = v;
        cs += v; css += v * v;
    }
    g_psum[blockIdx.x * H_ + j] = cs;
    g_pss[blockIdx.x * H_ + j]  = css;
}

__global__ void k_mlp3(const float* __restrict__ w1, const float* __restrict__ b1,
                       const float* __restrict__ w2, const float* __restrict__ b2) {
    extern __shared__ float sm[];
    float* sW = sm;
    float* sX = sm + 16384;
    float* sH = sX + 32 * 128;
    int tid = threadIdx.x;
    int row0 = blockIdx.x * 32;
    for (int i = tid; i < 16384; i += 128) sW[i] = w1[i];
    for (int i = tid; i < 32 * 128; i += 128) {
        int rr = i >> 7, j = i & 127;
        sX[i] = g_agg[(row0 + rr) * H_ + j] * (g_ab[2][j] * (1.f / 63.f)) + g_ab[3][j];
    }
    __syncthreads();
    int j = tid;
    float bj = b1[j];
    for (int rr = 0; rr < 32; rr++) {
        float acc = bj;
#pragma unroll 8
        for (int k = 0; k < 128; k++) acc += sX[rr * 128 + k] * sW[k * 128 + j];
        sH[rr * 128 + j] = eluf(acc);
    }
    __syncthreads();
    for (int i = tid; i < 16384; i += 128) sW[i] = w2[i];
    __syncthreads();
    float bj2 = b2[j], cs = 0.f, css = 0.f;
    for (int rr = 0; rr < 32; rr++) {
        float acc = bj2;
#pragma unroll 8
        for (int k = 0; k < 128; k++) acc += sH[rr * 128 + k] * sW[k * 128 + j];
        float v = eluf(acc);
        g_t3[(row0 + rr) * H_ + j] = v;
        cs += v; css += v * v;
    }
    g_psum[blockIdx.x * H_ + j] = cs;
    g_pss[blockIdx.x * H_ + j]  = css;
}

__global__ void k_stats(int nblk, float invcnt, const float* __restrict__ g,
                        const float* __restrict__ beta, int sel) {
    __shared__ float s1[256], s2[256];
    int col = blockIdx.x, tid = threadIdx.x;
    float s = 0.f, ss = 0.f;
    for (int i = tid; i < nblk; i += 256) { s += g_psum[i * H_ + col]; ss += g_pss[i * H_ + col]; }
    s1[tid] = s; s2[tid] = ss;
    __syncthreads();
    for (int o = 128; o > 0; o >>= 1) {
        if (tid < o) { s1[tid] += s1[tid + o]; s2[tid] += s2[tid + o]; }
        __syncthreads();
    }
    if (tid == 0) {
        float mu = s1[0] * invcnt;
        float var = s2[0] * invcnt - mu * mu;
        float a = rsqrtf(var + EPS_) * g[col];
        g_ab[2 * sel][col] = a;
        g_ab[2 * sel + 1][col] = beta[col] - mu * a;
    }
}

__global__ void k_pair(const float* __restrict__ w, int sel) {
    extern __shared__ float sm[];
    float* sW = sm;
    float* sX = sm + 16384;
    const float* tin = sel ? g_t3 : g_t1;
    const float* a   = sel ? g_ab[4] : g_ab[0];
    const float* c   = sel ? g_ab[5] : g_ab[1];
    float* O1 = sel ? g_R : g_P;
    float* O2 = sel ? g_S : g_Q;
    int tid = threadIdx.x;
    int row0 = blockIdx.x * 32;
    for (int i = tid; i < 32 * 128; i += 128) {
        int rr = i >> 7, j = i & 127;
        sX[i] = tin[(row0 + rr) * H_ + j] * a[j] + c[j];
    }
    for (int i = tid; i < 16384; i += 128) sW[i] = w[i];
    __syncthreads();
    int j = tid;
    for (int rr = 0; rr < 32; rr++) {
        float acc = 0.f;
#pragma unroll 8
        for (int k = 0; k < 128; k++) acc += sX[rr * 128 + k] * sW[k * 128 + j];
        O1[(row0 + rr) * H_ + j] = acc;
    }
    __syncthreads();
    for (int i = tid; i < 16384; i += 128) sW[i] = w[16384 + i];
    __syncthreads();
    for (int rr = 0; rr < 32; rr++) {
        float acc = 0.f;
#pragma unroll 8
        for (int k = 0; k < 128; k++) acc += sX[rr * 128 + k] * sW[k * 128 + j];
        O2[(row0 + rr) * H_ + j] = acc;
    }
}

// ---------------- edge stage B (128-row tiles, 8x8 threads) ----------------
// smem floats: sW dbuf [0,8192) | sXT [8192, 8192+128*XS_) | sIdx int2[128]
__global__ void __launch_bounds__(256, 2)
k_edge2(const float* __restrict__ W, const float* __restrict__ b1v,
        const float* __restrict__ b2v) {
    extern __shared__ float sm[];
    float* sW  = sm;
    float* sXT = sm + 8192;
    int2*  sIdx = (int2*)(sm + 8192 + 128 * XS_);
    int tid = threadIdx.x;
    int row0 = blockIdx.x * 128;
    if (tid < 128) {
        int b, s, r;
        decode_edge(row0 + tid, b, s, r);
        sIdx[tid] = make_int2(((b << 6) + s) << 7, ((b << 6) + r) << 7);
    }
    __syncthreads();
    {   // fill sXT transposed: thread (k, mh) covers 16 m-chunks of 4
        int k = tid & 127, mh = tid >> 7;
        float bk = b1v[k];
#pragma unroll 4
        for (int ch = 0; ch < 16; ch++) {
            int m = (ch * 2 + mh) * 4;
            int2 i0 = sIdx[m], i1 = sIdx[m + 1], i2 = sIdx[m + 2], i3 = sIdx[m + 3];
            float4 v;
            v.x = eluf(g_P[i0.x + k] + g_Q[i0.y + k] + bk);
            v.y = eluf(g_P[i1.x + k] + g_Q[i1.y + k] + bk);
            v.z = eluf(g_P[i2.x + k] + g_Q[i2.y + k] + bk);
            v.w = eluf(g_P[i3.x + k] + g_Q[i3.y + k] + bk);
            *(float4*)(sXT + k * XS_ + m) = v;
        }
    }
    int wid = tid >> 5, lane = tid & 31;
    int m0 = (wid & 1) * 64 + (lane >> 2) * 8;
    int c0 = (wid >> 1) * 32 + (lane & 3) * 8;
    float2 acc[4][8];
#pragma unroll
    for (int mi = 0; mi < 4; mi++)
#pragma unroll
        for (int ni = 0; ni < 8; ni++) acc[mi][ni] = make_float2(0.f, 0.f);
    gemm_streamW8(sW, sXT, W, tid, m0, c0, acc);

    float4 bb0 = *(const float4*)(b2v + c0);
    float4 bb1 = *(const float4*)(b2v + c0 + 4);
    float bv[8] = {bb0.x, bb0.y, bb0.z, bb0.w, bb1.x, bb1.y, bb1.z, bb1.w};
#pragma unroll
    for (int mi = 0; mi < 4; mi++) {
        int rA = row0 + m0 + 2 * mi;
        float oA[8], oB[8];
#pragma unroll
        for (int ni = 0; ni < 8; ni++) {
            oA[ni] = eluf(acc[mi][ni].x + bv[ni]);
            oB[ni] = eluf(acc[mi][ni].y + bv[ni]);
        }
        *(float4*)(g_skip + rA * H_ + c0)           = make_float4(oA[0], oA[1], oA[2], oA[3]);
        *(float4*)(g_skip + rA * H_ + c0 + 4)       = make_float4(oA[4], oA[5], oA[6], oA[7]);
        *(float4*)(g_skip + (rA + 1) * H_ + c0)     = make_float4(oB[0], oB[1], oB[2], oB[3]);
        *(float4*)(g_skip + (rA + 1) * H_ + c0 + 4) = make_float4(oB[4], oB[5], oB[6], oB[7]);
    }
}

// ---------------- edge stage D (fused, 128-row tiles, 8x8 threads) ----------------
__global__ void __launch_bounds__(256, 2)
k_edge4(const float* __restrict__ W42, const float* __restrict__ b42) {
    extern __shared__ float sm[];
    float* sW  = sm;
    float* sXT = sm + 8192;
    int2*  sIdx = (int2*)(sm + 8192 + 128 * XS_);
    int tid = threadIdx.x;
    int row0 = blockIdx.x * 128;
    if (tid < 128) {
        int b, s, r;
        decode_edge(row0 + tid, b, s, r);
        sIdx[tid] = make_int2(((b << 6) + s) << 7, ((b << 6) + r) << 7);
    }
    {   // fill sXT transposed from g_skip
        int k = tid & 127, mh = tid >> 7;
#pragma unroll 4
        for (int ch = 0; ch < 16; ch++) {
            int m = (ch * 2 + mh) * 4;
            const float* ps = g_skip + (row0 + m) * H_ + k;
            *(float4*)(sXT + k * XS_ + m) =
                make_float4(ps[0], ps[128], ps[256], ps[384]);
        }
    }
    int wid = tid >> 5, lane = tid & 31;
    int m0 = (wid & 1) * 64 + (lane >> 2) * 8;
    int c0 = (wid >> 1) * 32 + (lane & 3) * 8;
    int g = lane >> 2;
    float2 acc[4][8];
#pragma unroll
    for (int mi = 0; mi < 4; mi++)
#pragma unroll
        for (int ni = 0; ni < 8; ni++) acc[mi][ni] = make_float2(0.f, 0.f);
    gemm_streamW8(sW, sXT, g_Wcp, tid, m0, c0, acc);   // ends synced

    // epilogue 1: h3 = ELU(acc + R[s] + S[r] + bias4) -> transposed into sXT (staggered cols)
    {
        float4 b40 = *(const float4*)(g_bias4 + c0);
        float4 b41v = *(const float4*)(g_bias4 + c0 + 4);
        float b4[8] = {b40.x, b40.y, b40.z, b40.w, b41v.x, b41v.y, b41v.z, b41v.w};
#pragma unroll
        for (int mi = 0; mi < 4; mi++) {
            int mA = m0 + 2 * mi;
            int2 iA = sIdx[mA], iB = sIdx[mA + 1];
            float4 ra0 = *(const float4*)(g_R + iA.x + c0);
            float4 ra1 = *(const float4*)(g_R + iA.x + c0 + 4);
            float4 sa0 = *(const float4*)(g_S + iA.y + c0);
            float4 sa1 = *(const float4*)(g_S + iA.y + c0 + 4);
            float4 rb0 = *(const float4*)(g_R + iB.x + c0);
            float4 rb1 = *(const float4*)(g_R + iB.x + c0 + 4);
            float4 sb0 = *(const float4*)(g_S + iB.y + c0);
            float4 sb1 = *(const float4*)(g_S + iB.y + c0 + 4);
            float ra[8] = {ra0.x, ra0.y, ra0.z, ra0.w, ra1.x, ra1.y, ra1.z, ra1.w};
            float sa[8] = {sa0.x, sa0.y, sa0.z, sa0.w, sa1.x, sa1.y, sa1.z, sa1.w};
            float rb[8] = {rb0.x, rb0.y, rb0.z, rb0.w, rb1.x, rb1.y, rb1.z, rb1.w};
            float sb[8] = {sb0.x, sb0.y, sb0.z, sb0.w, sb1.x, sb1.y, sb1.z, sb1.w};
#pragma unroll
            for (int ni = 0; ni < 8; ni++) {
                int j = (ni + g) & 7;   // stagger to reduce bank conflicts
                float hx = eluf(acc[mi][j].x + ra[j] + sa[j] + b4[j]);
                float hy = eluf(acc[mi][j].y + rb[j] + sb[j] + b4[j]);
                *(float2*)(sXT + (c0 + j) * XS_ + mA) = make_float2(hx, hy);
            }
        }
    }
#pragma unroll
    for (int mi = 0; mi < 4; mi++)
#pragma unroll
        for (int ni = 0; ni < 8; ni++) acc[mi][ni] = make_float2(0.f, 0.f);
    gemm_streamW8(sW, sXT, W42, tid, m0, c0, acc);     // first sync guards sXT writes

    // epilogue 2: h4 = ELU(acc + b42) -> gmem + BN4 stats partials
    float4 bb0 = *(const float4*)(b42 + c0);
    float4 bb1 = *(const float4*)(b42 + c0 + 4);
    float bv[8] = {bb0.x, bb0.y, bb0.z, bb0.w, bb1.x, bb1.y, bb1.z, bb1.w};
    float cs[8], css[8];
#pragma unroll
    for (int ni = 0; ni < 8; ni++) { cs[ni] = 0.f; css[ni] = 0.f; }
#pragma unroll
    for (int mi = 0; mi < 4; mi++) {
        int rA = row0 + m0 + 2 * mi;
        float oA[8], oB[8];
#pragma unroll
        for (int ni = 0; ni < 8; ni++) {
            oA[ni] = eluf(acc[mi][ni].x + bv[ni]);
            oB[ni] = eluf(acc[mi][ni].y + bv[ni]);
            cs[ni] += oA[ni] + oB[ni];
            css[ni] += oA[ni] * oA[ni] + oB[ni] * oB[ni];
        }
        *(float4*)(g_h4 + rA * H_ + c0)           = make_float4(oA[0], oA[1], oA[2], oA[3]);
        *(float4*)(g_h4 + rA * H_ + c0 + 4)       = make_float4(oA[4], oA[5], oA[6], oA[7]);
        *(float4*)(g_h4 + (rA + 1) * H_ + c0)     = make_float4(oB[0], oB[1], oB[2], oB[3]);
        *(float4*)(g_h4 + (rA + 1) * H_ + c0 + 4) = make_float4(oB[4], oB[5], oB[6], oB[7]);
    }
    // deterministic stats reduction: 16 m-slots x 128 cols (float2), in sW region
    float2* sRed = (float2*)sm;
    int slot = (wid & 1) * 8 + g;
    __syncthreads();
#pragma unroll
    for (int ni = 0; ni < 8; ni++)
        sRed[slot * 128 + c0 + ni] = make_float2(cs[ni], css[ni]);
    __syncthreads();
    if (tid < 128) {
        float ps = 0.f, pss = 0.f;
#pragma unroll
        for (int s16 = 0; s16 < 16; s16++) {
            float2 v = sRed[s16 * 128 + tid];
            ps += v.x; pss += v.y;
        }
        g_psum[blockIdx.x * H_ + tid] = ps;
        g_pss[blockIdx.x * H_ + tid]  = pss;
    }
}

// edge2node deterministic segment-sum + BN2 stats partials
__global__ void k_agg() {
    int b = blockIdx.x >> 6, r = blockIdx.x & 63, j = threadIdx.x;
    const float* base = g_skip + (b * E_) * H_ + j;
    float s = 0.f, css = 0.f;
#pragma unroll 7
    for (int m = 0; m < 63; m++) {
        int i = m + (m >= r ? 1 : 0);
        int e = i * 63 + (m < r ? r - 1 : r);
        float v = base[e * H_];
        s += v; css += v * v;
    }
    g_agg[(b * N_ + r) * H_ + j] = s;
    g_psum[blockIdx.x * H_ + j] = s;
    g_pss[blockIdx.x * H_ + j]  = css;
}

// fold BN2 into skip slice of mlp4_w1
__global__ void k_wcp(const float* __restrict__ w41) {
    int k = blockIdx.x, j = threadIdx.x;
    g_Wcp[k * H_ + j] = g_ab[2][k] * w41[(256 + k) * H_ + j];
}
__global__ void k_bias4(const float* __restrict__ w41, const float* __restrict__ b41) {
    int j = threadIdx.x;
    float acc = b41[j];
    for (int k = 0; k < 128; k++) acc += g_ab[3][k] * w41[(256 + k) * H_ + j];
    g_bias4[j] = acc;
}

// fold BN4 into fc
__global__ void k_foldfc(const float* __restrict__ fcw, const float* __restrict__ fcb) {
    int j = threadIdx.x;
    g_fw[j * 2 + 0] = g_ab[6][j] * fcw[j * 2 + 0];
    g_fw[j * 2 + 1] = g_ab[6][j] * fcw[j * 2 + 1];
    if (j < 2) {
        float acc = fcb[j];
        for (int k = 0; k < 128; k++) acc += g_ab[7][k] * fcw[k * 2 + j];
        g_fb[j] = acc;
    }
}

// final logits: warp per row
__global__ void k_fc(float* __restrict__ out) {
    int w = (blockIdx.x * blockDim.x + threadIdx.x) >> 5;
    int lane = threadIdx.x & 31;
    if (w >= BE_) return;
    float4 h   = *(const float4*)(g_h4 + w * H_ + lane * 4);
    float4 fa  = *(const float4*)(g_fw + lane * 8);
    float4 fb4 = *(const float4*)(g_fw + lane * 8 + 4);
    float s0 = h.x * fa.x + h.y * fa.z + h.z * fb4.x + h.w * fb4.z;
    float s1 = h.x * fa.y + h.y * fa.w + h.z * fb4.y + h.w * fb4.w;
    for (int o = 16; o > 0; o >>= 1) {
        s0 += __shfl_xor_sync(0xffffffffu, s0, o);
        s1 += __shfl_xor_sync(0xffffffffu, s1, o);
    }
    if (lane == 0) *(float2*)(out + w * 2) = make_float2(s0 + g_fb[0], s1 + g_fb[1]);
}

// ---------------- host ----------------
extern "C" void kernel_launch(void* const* d_in, const int* in_sizes, int n_in,
                              void* d_out, int out_size) {
    const float* inp = (const float*)d_in[0];
    const float* w11 = (const float*)d_in[1];  const float* b11 = (const float*)d_in[2];
    const float* w12 = (const float*)d_in[3];  const float* b12 = (const float*)d_in[4];
    const float* g1  = (const float*)d_in[5];  const float* be1 = (const float*)d_in[6];
    const float* w21 = (const float*)d_in[7];  const float* b21 = (const float*)d_in[8];
    const float* w22 = (const float*)d_in[9];  const float* b22 = (const float*)d_in[10];
    const float* g2  = (const float*)d_in[11]; const float* be2 = (const float*)d_in[12];
    const float* w31 = (const float*)d_in[13]; const float* b31 = (const float*)d_in[14];
    const float* w32 = (const float*)d_in[15]; const float* b32 = (const float*)d_in[16];
    const float* g3  = (const float*)d_in[17]; const float* be3 = (const float*)d_in[18];
    const float* w41 = (const float*)d_in[19]; const float* b41 = (const float*)d_in[20];
    const float* w42 = (const float*)d_in[21]; const float* b42 = (const float*)d_in[22];
    const float* g4  = (const float*)d_in[23]; const float* be4 = (const float*)d_in[24];
    const float* fcw = (const float*)d_in[25]; const float* fcb = (const float*)d_in[26];
    float* out = (float*)d_out;

    const int SM_MLP1 = (16384 + 32 * 40 + 32 * 128) * 4;
    const int SM_MLP3 = (16384 + 32 * 128 + 32 * 128) * 4;
    const int SM_PAIR = (16384 + 32 * 128) * 4;
    const int SM_EDGE = (8192 + 128 * XS_ + 256) * 4;   // 101376 B -> 2 blocks/SM

    cudaFuncSetAttribute(k_mlp1,  cudaFuncAttributeMaxDynamicSharedMemorySize, SM_MLP1);
    cudaFuncSetAttribute(k_mlp3,  cudaFuncAttributeMaxDynamicSharedMemorySize, SM_MLP3);
    cudaFuncSetAttribute(k_pair,  cudaFuncAttributeMaxDynamicSharedMemorySize, SM_PAIR);
    cudaFuncSetAttribute(k_edge2, cudaFuncAttributeMaxDynamicSharedMemorySize, SM_EDGE);
    cudaFuncSetAttribute(k_edge4, cudaFuncAttributeMaxDynamicSharedMemorySize, SM_EDGE);

    k_mlp1<<<128, 128, SM_MLP1>>>(inp, w11, b11, w12, b12);
    k_stats<<<128, 256>>>(128, 1.f / 4096.f, g1, be1, 0);
    k_pair<<<128, 128, SM_PAIR>>>(w21, 0);
    k_edge2<<<2016, 256, SM_EDGE>>>(w22, b21, b22);
    k_agg<<<4096, 128>>>();
    k_stats<<<128, 256>>>(4096, 1.f / 258048.f, g2, be2, 1);
    k_mlp3<<<128, 128, SM_MLP3>>>(w31, b31, w32, b32);
    k_stats<<<128, 256>>>(128, 1.f / 4096.f, g3, be3, 2);
    k_pair<<<128, 128, SM_PAIR>>>(w41, 1);
    k_wcp<<<128, 128>>>(w41);
    k_bias4<<<1, 128>>>(w41, b41);
    k_edge4<<<2016, 256, SM_EDGE>>>(w42, b42);
    k_stats<<<128, 256>>>(2016, 1.f / 258048.f, g4, be4, 3);
    k_foldfc<<<1, 128>>>(fcw, fcb);
    k_fc<<<BE_ * 32 / 256, 256>>>(out);
}

// round 10
// speedup vs baseline: 1.5481x; 1.5481x over previous
#include <cuda_runtime.h>

#define H_   128
#define B_   64
#define T_   10
#define N_   64
#define D_   4
#define E_   4032
#define BE_  258048
#define BN_  4096
#define EPS_ 1e-5f
#define XS_  68   // smem transposed-tile stride (floats)

// ---------------- device scratch ----------------
__device__ __align__(16) float g_t1[BN_ * H_];
__device__ __align__(16) float g_P[BN_ * H_];
__device__ __align__(16) float g_Q[BN_ * H_];
__device__ __align__(16) float g_skip[BE_ * H_];   // pre-BN mlp2 output
__device__ __align__(16) float g_h4[BE_ * H_];     // pre-BN mlp4 output
__device__ __align__(16) float g_agg[BN_ * H_];
__device__ __align__(16) float g_t3[BN_ * H_];
__device__ __align__(16) float g_R[BN_ * H_];
__device__ __align__(16) float g_S[BN_ * H_];
__device__ __align__(16) float g_psum[BN_ * H_];
__device__ __align__(16) float g_pss[BN_ * H_];
__device__ __align__(16) float g_ab[8][H_];        // a1,c1,a2,c2,a3,c3,a4,c4
__device__ __align__(16) float g_Wcp[H_ * H_];
__device__ __align__(16) float g_bias4[H_];
__device__ __align__(16) float g_fw[H_ * 2];
__device__ __align__(16) float g_fb[2];

// ---------------- helpers ----------------
__device__ __forceinline__ float eluf(float x) {
    return x > 0.f ? x : (__expf(x) - 1.f);
}

// packed dual fp32 FMA (Blackwell f32x2): c = a * (b,b) + c
__device__ __forceinline__ float2 ffma2s(float2 a, float bs, float2 c) {
    float2 b = make_float2(bs, bs);
    unsigned long long au = *reinterpret_cast<unsigned long long*>(&a);
    unsigned long long bu = *reinterpret_cast<unsigned long long*>(&b);
    unsigned long long cu = *reinterpret_cast<unsigned long long*>(&c);
    asm("fma.rn.f32x2 %0, %1, %2, %0;" : "+l"(cu) : "l"(au), "l"(bu));
    return *reinterpret_cast<float2*>(&cu);
}

__device__ __forceinline__ void decode_edge(int gr, int& b, int& s, int& r) {
    b = gr / E_;
    int e = gr - b * E_;
    s = e / 63;
    int jj = e - s * 63;
    r = jj + (jj >= s ? 1 : 0);
}

// full K=128 GEMM: activations from smem (transposed tile), weights streamed
// from global through L1 (identical across blocks -> L1-resident). No syncs.
__device__ __forceinline__ void gemm_gW(const float* __restrict__ W, const float* sXT,
                                        int m0, int c0, float2 acc[16]) {
    const float4* __restrict__ Wp = (const float4*)(W + c0);   // Wp[k*32]
#pragma unroll 4
    for (int k = 0; k < 128; k++) {
        float4 w  = __ldg(Wp + k * 32);
        float4 ha = *(const float4*)(sXT + k * XS_ + m0);
        float4 hb = *(const float4*)(sXT + k * XS_ + m0 + 4);
        float2 h0 = make_float2(ha.x, ha.y), h1 = make_float2(ha.z, ha.w);
        float2 h2 = make_float2(hb.x, hb.y), h3 = make_float2(hb.z, hb.w);
        acc[0]  = ffma2s(h0, w.x, acc[0]);  acc[1]  = ffma2s(h0, w.y, acc[1]);
        acc[2]  = ffma2s(h0, w.z, acc[2]);  acc[3]  = ffma2s(h0, w.w, acc[3]);
        acc[4]  = ffma2s(h1, w.x, acc[4]);  acc[5]  = ffma2s(h1, w.y, acc[5]);
        acc[6]  = ffma2s(h1, w.z, acc[6]);  acc[7]  = ffma2s(h1, w.w, acc[7]);
        acc[8]  = ffma2s(h2, w.x, acc[8]);  acc[9]  = ffma2s(h2, w.y, acc[9]);
        acc[10] = ffma2s(h2, w.z, acc[10]); acc[11] = ffma2s(h2, w.w, acc[11]);
        acc[12] = ffma2s(h3, w.x, acc[12]); acc[13] = ffma2s(h3, w.y, acc[13]);
        acc[14] = ffma2s(h3, w.z, acc[14]); acc[15] = ffma2s(h3, w.w, acc[15]);
    }
}

// ---------------- node-level kernels (4096 rows, 256 blocks x 16 rows) ----------------
__global__ void k_mlp1(const float* __restrict__ inp, const float* __restrict__ w1,
                       const float* __restrict__ b1, const float* __restrict__ w2,
                       const float* __restrict__ b2) {
    extern __shared__ float sm[];
    float* sW = sm;
    float* sX = sm + 16384;
    float* sH = sX + 16 * 40;
    int tid = threadIdx.x;
    int row0 = blockIdx.x * 16;
    for (int i = tid; i < 40 * 128; i += 128) sW[i] = w1[i];
    for (int i = tid; i < 16 * 40; i += 128) {
        int rr = i / 40, k = i - rr * 40;
        int row = row0 + rr, b = row >> 6, n = row & 63;
        int t = k >> 2, d = k & 3;
        sX[i] = inp[((b * T_ + t) * N_ + n) * D_ + d];
    }
    __syncthreads();
    int j = tid;
    float bj = b1[j];
    for (int rr = 0; rr < 16; rr++) {
        float acc = bj;
        for (int k = 0; k < 40; k++) acc += sX[rr * 40 + k] * sW[k * 128 + j];
        sH[rr * 128 + j] = eluf(acc);
    }
    __syncthreads();
    for (int i = tid; i < 16384; i += 128) sW[i] = w2[i];
    __syncthreads();
    float bj2 = b2[j], cs = 0.f, css = 0.f;
    for (int rr = 0; rr < 16; rr++) {
        float acc = bj2;
#pragma unroll 8
        for (int k = 0; k < 128; k++) acc += sH[rr * 128 + k] * sW[k * 128 + j];
        float v = eluf(acc);
        g_t1[(row0 + rr) * H_ + j] = v;
        cs += v; css += v * v;
    }
    g_psum[blockIdx.x * H_ + j] = cs;
    g_pss[blockIdx.x * H_ + j]  = css;
}

__global__ void k_mlp3(const float* __restrict__ w1, const float* __restrict__ b1,
                       const float* __restrict__ w2, const float* __restrict__ b2) {
    extern __shared__ float sm[];
    float* sW = sm;
    float* sX = sm + 16384;
    float* sH = sX + 16 * 128;
    int tid = threadIdx.x;
    int row0 = blockIdx.x * 16;
    for (int i = tid; i < 16384; i += 128) sW[i] = w1[i];
    for (int i = tid; i < 16 * 128; i += 128) {
        int rr = i >> 7, j = i & 127;
        sX[i] = g_agg[(row0 + rr) * H_ + j] * (g_ab[2][j] * (1.f / 63.f)) + g_ab[3][j];
    }
    __syncthreads();
    int j = tid;
    float bj = b1[j];
    for (int rr = 0; rr < 16; rr++) {
        float acc = bj;
#pragma unroll 8
        for (int k = 0; k < 128; k++) acc += sX[rr * 128 + k] * sW[k * 128 + j];
        sH[rr * 128 + j] = eluf(acc);
    }
    __syncthreads();
    for (int i = tid; i < 16384; i += 128) sW[i] = w2[i];
    __syncthreads();
    float bj2 = b2[j], cs = 0.f, css = 0.f;
    for (int rr = 0; rr < 16; rr++) {
        float acc = bj2;
#pragma unroll 8
        for (int k = 0; k < 128; k++) acc += sH[rr * 128 + k] * sW[k * 128 + j];
        float v = eluf(acc);
        g_t3[(row0 + rr) * H_ + j] = v;
        cs += v; css += v * v;
    }
    g_psum[blockIdx.x * H_ + j] = cs;
    g_pss[blockIdx.x * H_ + j]  = css;
}

__global__ void k_stats(int nblk, float invcnt, const float* __restrict__ g,
                        const float* __restrict__ beta, int sel) {
    __shared__ float s1[256], s2[256];
    int col = blockIdx.x, tid = threadIdx.x;
    float s = 0.f, ss = 0.f;
    for (int i = tid; i < nblk; i += 256) { s += g_psum[i * H_ + col]; ss += g_pss[i * H_ + col]; }
    s1[tid] = s; s2[tid] = ss;
    __syncthreads();
    for (int o = 128; o > 0; o >>= 1) {
        if (tid < o) { s1[tid] += s1[tid + o]; s2[tid] += s2[tid + o]; }
        __syncthreads();
    }
    if (tid == 0) {
        float mu = s1[0] * invcnt;
        float var = s2[0] * invcnt - mu * mu;
        float a = rsqrtf(var + EPS_) * g[col];
        g_ab[2 * sel][col] = a;
        g_ab[2 * sel + 1][col] = beta[col] - mu * a;
    }
}

__global__ void k_pair(const float* __restrict__ w, int sel) {
    extern __shared__ float sm[];
    float* sW = sm;
    float* sX = sm + 16384;
    const float* tin = sel ? g_t3 : g_t1;
    const float* a   = sel ? g_ab[4] : g_ab[0];
    const float* c   = sel ? g_ab[5] : g_ab[1];
    float* O1 = sel ? g_R : g_P;
    float* O2 = sel ? g_S : g_Q;
    int tid = threadIdx.x;
    int row0 = blockIdx.x * 16;
    for (int i = tid; i < 16 * 128; i += 128) {
        int rr = i >> 7, j = i & 127;
        sX[i] = tin[(row0 + rr) * H_ + j] * a[j] + c[j];
    }
    for (int i = tid; i < 16384; i += 128) sW[i] = w[i];
    __syncthreads();
    int j = tid;
    for (int rr = 0; rr < 16; rr++) {
        float acc = 0.f;
#pragma unroll 8
        for (int k = 0; k < 128; k++) acc += sX[rr * 128 + k] * sW[k * 128 + j];
        O1[(row0 + rr) * H_ + j] = acc;
    }
    __syncthreads();
    for (int i = tid; i < 16384; i += 128) sW[i] = w[16384 + i];
    __syncthreads();
    for (int rr = 0; rr < 16; rr++) {
        float acc = 0.f;
#pragma unroll 8
        for (int k = 0; k < 128; k++) acc += sX[rr * 128 + k] * sW[k * 128 + j];
        O2[(row0 + rr) * H_ + j] = acc;
    }
}

// ---------------- edge stage B: skip_pre = ELU(ELU(P[s]+Q[r]+b1) @ W2 + b2) ----------------
// smem: sXT only (128 k x 64 m transposed tile)
__global__ void __launch_bounds__(256, 3)
k_edge2(const float* __restrict__ W, const float* __restrict__ b1v,
        const float* __restrict__ b2v) {
    extern __shared__ float sm[];
    float* sXT = sm;
    int tid = threadIdx.x;
    int row0 = blockIdx.x * 64;
    {
        int k = tid & 127, mh = tid >> 7;
        float bk = b1v[k];
        for (int m = mh; m < 64; m += 2) {
            int gr = row0 + m, b, s, r;
            decode_edge(gr, b, s, r);
            sXT[k * XS_ + m] = eluf(g_P[((b << 6) + s) * H_ + k] +
                                    g_Q[((b << 6) + r) * H_ + k] + bk);
        }
    }
    __syncthreads();
    // 2-D warp tiling: warp = 32m x 32n, thread = 8m x 4n
    int m0 = ((tid >> 5) & 1) * 32 + ((tid & 31) >> 3) * 8;
    int c0 = (tid >> 6) * 32 + (tid & 7) * 4;
    float2 acc[16];
#pragma unroll
    for (int i = 0; i < 16; i++) acc[i] = make_float2(0.f, 0.f);
    gemm_gW(W, sXT, m0, c0, acc);

    float4 bias = *(const float4*)(b2v + c0);
#pragma unroll
    for (int p = 0; p < 4; p++) {
        int rA = row0 + m0 + 2 * p;
        float4 va, vb;
        va.x = eluf(acc[p * 4 + 0].x + bias.x); va.y = eluf(acc[p * 4 + 1].x + bias.y);
        va.z = eluf(acc[p * 4 + 2].x + bias.z); va.w = eluf(acc[p * 4 + 3].x + bias.w);
        vb.x = eluf(acc[p * 4 + 0].y + bias.x); vb.y = eluf(acc[p * 4 + 1].y + bias.y);
        vb.z = eluf(acc[p * 4 + 2].y + bias.z); vb.w = eluf(acc[p * 4 + 3].y + bias.w);
        *(float4*)(g_skip + rA * H_ + c0) = va;
        *(float4*)(g_skip + (rA + 1) * H_ + c0) = vb;
    }
}

// ---------------- edge stage D (fused): two GEMMs, h3 stays on-chip ----------------
// smem: sXT (128 x XS_) then sRed (8 x 128)
__global__ void __launch_bounds__(256, 3)
k_edge4(const float* __restrict__ W42, const float* __restrict__ b42) {
    extern __shared__ float sm[];
    float* sXT  = sm;
    float* sRed = sm + XS_ * 128;
    int tid = threadIdx.x;
    int row0 = blockIdx.x * 64;
    {
        int k = tid & 127, mh = tid >> 7;
        for (int m = mh; m < 64; m += 2)
            sXT[k * XS_ + m] = g_skip[(row0 + m) * H_ + k];
    }
    __syncthreads();
    int m0 = ((tid >> 5) & 1) * 32 + ((tid & 31) >> 3) * 8;
    int c0 = (tid >> 6) * 32 + (tid & 7) * 4;
    float2 acc[16];
#pragma unroll
    for (int i = 0; i < 16; i++) acc[i] = make_float2(0.f, 0.f);
    gemm_gW(g_Wcp, sXT, m0, c0, acc);
    __syncthreads();   // all sXT reads done before overwrite

    // epilogue 1: h3 = ELU(acc + R[s] + S[r] + bias4), write TRANSPOSED into sXT
    {
        float4 b4v = *(const float4*)(g_bias4 + c0);
#pragma unroll
        for (int p = 0; p < 4; p++) {
            int rA = row0 + m0 + 2 * p, rB = rA + 1;
            int bA, sA, rcA, bB, sB, rcB;
            decode_edge(rA, bA, sA, rcA);
            decode_edge(rB, bB, sB, rcB);
            float4 RA = *(const float4*)(g_R + ((bA << 6) + sA) * H_ + c0);
            float4 SA = *(const float4*)(g_S + ((bA << 6) + rcA) * H_ + c0);
            float4 RB = *(const float4*)(g_R + ((bB << 6) + sB) * H_ + c0);
            float4 SB = *(const float4*)(g_S + ((bB << 6) + rcB) * H_ + c0);
            int mA = m0 + 2 * p, mB = mA + 1;
            sXT[(c0 + 0) * XS_ + mA] = eluf(acc[p * 4 + 0].x + RA.x + SA.x + b4v.x);
            sXT[(c0 + 1) * XS_ + mA] = eluf(acc[p * 4 + 1].x + RA.y + SA.y + b4v.y);
            sXT[(c0 + 2) * XS_ + mA] = eluf(acc[p * 4 + 2].x + RA.z + SA.z + b4v.z);
            sXT[(c0 + 3) * XS_ + mA] = eluf(acc[p * 4 + 3].x + RA.w + SA.w + b4v.w);
            sXT[(c0 + 0) * XS_ + mB] = eluf(acc[p * 4 + 0].y + RB.x + SB.x + b4v.x);
            sXT[(c0 + 1) * XS_ + mB] = eluf(acc[p * 4 + 1].y + RB.y + SB.y + b4v.y);
            sXT[(c0 + 2) * XS_ + mB] = eluf(acc[p * 4 + 2].y + RB.z + SB.z + b4v.z);
            sXT[(c0 + 3) * XS_ + mB] = eluf(acc[p * 4 + 3].y + RB.w + SB.w + b4v.w);
        }
    }
    __syncthreads();   // sXT writes visible before phase-2 reads
#pragma unroll
    for (int i = 0; i < 16; i++) acc[i] = make_float2(0.f, 0.f);
    gemm_gW(W42, sXT, m0, c0, acc);

    // epilogue 2: h4 = ELU(acc + b42) -> gmem, + BN4 stats partials
    float4 bias = *(const float4*)(b42 + c0);
    float cs[4] = {0, 0, 0, 0}, css[4] = {0, 0, 0, 0};
#pragma unroll
    for (int p = 0; p < 4; p++) {
        int rA = row0 + m0 + 2 * p;
        float4 va, vb;
        va.x = eluf(acc[p * 4 + 0].x + bias.x); va.y = eluf(acc[p * 4 + 1].x + bias.y);
        va.z = eluf(acc[p * 4 + 2].x + bias.z); va.w = eluf(acc[p * 4 + 3].x + bias.w);
        vb.x = eluf(acc[p * 4 + 0].y + bias.x); vb.y = eluf(acc[p * 4 + 1].y + bias.y);
        vb.z = eluf(acc[p * 4 + 2].y + bias.z); vb.w = eluf(acc[p * 4 + 3].y + bias.w);
        *(float4*)(g_h4 + rA * H_ + c0) = va;
        *(float4*)(g_h4 + (rA + 1) * H_ + c0) = vb;
        cs[0] += va.x + vb.x; css[0] += va.x * va.x + vb.x * vb.x;
        cs[1] += va.y + vb.y; css[1] += va.y * va.y + vb.y * vb.y;
        cs[2] += va.z + vb.z; css[2] += va.z * va.z + vb.z * vb.z;
        cs[3] += va.w + vb.w; css[3] += va.w * va.w + vb.w * vb.w;
    }
    int slot = ((tid >> 5) & 1) * 4 + ((tid & 31) >> 3);
    __syncthreads();
#pragma unroll
    for (int jj = 0; jj < 4; jj++) sRed[slot * 128 + c0 + jj] = cs[jj];
    __syncthreads();
    float ps = 0.f;
    if (tid < 128) for (int g8 = 0; g8 < 8; g8++) ps += sRed[g8 * 128 + tid];
    __syncthreads();
#pragma unroll
    for (int jj = 0; jj < 4; jj++) sRed[slot * 128 + c0 + jj] = css[jj];
    __syncthreads();
    if (tid < 128) {
        float pss = 0.f;
        for (int g8 = 0; g8 < 8; g8++) pss += sRed[g8 * 128 + tid];
        g_psum[blockIdx.x * H_ + tid] = ps;
        g_pss[blockIdx.x * H_ + tid]  = pss;
    }
}

// edge2node deterministic segment-sum + BN2 stats partials
__global__ void k_agg() {
    int b = blockIdx.x >> 6, r = blockIdx.x & 63, j = threadIdx.x;
    const float* base = g_skip + (b * E_) * H_ + j;
    float s = 0.f, css = 0.f;
#pragma unroll 7
    for (int m = 0; m < 63; m++) {
        int i = m + (m >= r ? 1 : 0);
        int e = i * 63 + (m < r ? r - 1 : r);
        float v = base[e * H_];
        s += v; css += v * v;
    }
    g_agg[(b * N_ + r) * H_ + j] = s;
    g_psum[blockIdx.x * H_ + j] = s;
    g_pss[blockIdx.x * H_ + j]  = css;
}

// fold BN2 into skip slice of mlp4_w1
__global__ void k_wcp(const float* __restrict__ w41) {
    int k = blockIdx.x, j = threadIdx.x;
    g_Wcp[k * H_ + j] = g_ab[2][k] * w41[(256 + k) * H_ + j];
}
__global__ void k_bias4(const float* __restrict__ w41, const float* __restrict__ b41) {
    int j = threadIdx.x;
    float acc = b41[j];
    for (int k = 0; k < 128; k++) acc += g_ab[3][k] * w41[(256 + k) * H_ + j];
    g_bias4[j] = acc;
}

// fold BN4 into fc
__global__ void k_foldfc(const float* __restrict__ fcw, const float* __restrict__ fcb) {
    int j = threadIdx.x;
    g_fw[j * 2 + 0] = g_ab[6][j] * fcw[j * 2 + 0];
    g_fw[j * 2 + 1] = g_ab[6][j] * fcw[j * 2 + 1];
    if (j < 2) {
        float acc = fcb[j];
        for (int k = 0; k < 128; k++) acc += g_ab[7][k] * fcw[k * 2 + j];
        g_fb[j] = acc;
    }
}

// final logits: warp per row
__global__ void k_fc(float* __restrict__ out) {
    int w = (blockIdx.x * blockDim.x + threadIdx.x) >> 5;
    int lane = threadIdx.x & 31;
    if (w >= BE_) return;
    float4 h   = *(const float4*)(g_h4 + w * H_ + lane * 4);
    float4 fa  = *(const float4*)(g_fw + lane * 8);
    float4 fb4 = *(const float4*)(g_fw + lane * 8 + 4);
    float s0 = h.x * fa.x + h.y * fa.z + h.z * fb4.x + h.w * fb4.z;
    float s1 = h.x * fa.y + h.y * fa.w + h.z * fb4.y + h.w * fb4.w;
    for (int o = 16; o > 0; o >>= 1) {
        s0 += __shfl_xor_sync(0xffffffffu, s0, o);
        s1 += __shfl_xor_sync(0xffffffffu, s1, o);
    }
    if (lane == 0) *(float2*)(out + w * 2) = make_float2(s0 + g_fb[0], s1 + g_fb[1]);
}

// ---------------- host ----------------
extern "C" void kernel_launch(void* const* d_in, const int* in_sizes, int n_in,
                              void* d_out, int out_size) {
    const float* inp = (const float*)d_in[0];
    const float* w11 = (const float*)d_in[1];  const float* b11 = (const float*)d_in[2];
    const float* w12 = (const float*)d_in[3];  const float* b12 = (const float*)d_in[4];
    const float* g1  = (const float*)d_in[5];  const float* be1 = (const float*)d_in[6];
    const float* w21 = (const float*)d_in[7];  const float* b21 = (const float*)d_in[8];
    const float* w22 = (const float*)d_in[9];  const float* b22 = (const float*)d_in[10];
    const float* g2  = (const float*)d_in[11]; const float* be2 = (const float*)d_in[12];
    const float* w31 = (const float*)d_in[13]; const float* b31 = (const float*)d_in[14];
    const float* w32 = (const float*)d_in[15]; const float* b32 = (const float*)d_in[16];
    const float* g3  = (const float*)d_in[17]; const float* be3 = (const float*)d_in[18];
    const float* w41 = (const float*)d_in[19]; const float* b41 = (const float*)d_in[20];
    const float* w42 = (const float*)d_in[21]; const float* b42 = (const float*)d_in[22];
    const float* g4  = (const float*)d_in[23]; const float* be4 = (const float*)d_in[24];
    const float* fcw = (const float*)d_in[25]; const float* fcb = (const float*)d_in[26];
    float* out = (float*)d_out;

    const int SM_MLP1 = (16384 + 16 * 40 + 16 * 128) * 4;
    const int SM_MLP3 = (16384 + 16 * 128 + 16 * 128) * 4;
    const int SM_PAIR = (16384 + 16 * 128) * 4;
    const int SM_E2   = (XS_ * 128) * 4;            // 34816 B
    const int SM_E4   = (XS_ * 128 + 1024) * 4;     // 38912 B

    cudaFuncSetAttribute(k_mlp1,  cudaFuncAttributeMaxDynamicSharedMemorySize, SM_MLP1);
    cudaFuncSetAttribute(k_mlp3,  cudaFuncAttributeMaxDynamicSharedMemorySize, SM_MLP3);
    cudaFuncSetAttribute(k_pair,  cudaFuncAttributeMaxDynamicSharedMemorySize, SM_PAIR);
    cudaFuncSetAttribute(k_edge2, cudaFuncAttributeMaxDynamicSharedMemorySize, SM_E2);
    cudaFuncSetAttribute(k_edge4, cudaFuncAttributeMaxDynamicSharedMemorySize, SM_E4);

    k_mlp1<<<256, 128, SM_MLP1>>>(inp, w11, b11, w12, b12);
    k_stats<<<128, 256>>>(256, 1.f / 4096.f, g1, be1, 0);
    k_pair<<<256, 128, SM_PAIR>>>(w21, 0);
    k_edge2<<<4032, 256, SM_E2>>>(w22, b21, b22);
    k_agg<<<4096, 128>>>();
    k_stats<<<128, 256>>>(4096, 1.f / 258048.f, g2, be2, 1);
    k_mlp3<<<256, 128, SM_MLP3>>>(w31, b31, w32, b32);
    k_stats<<<128, 256>>>(256, 1.f / 4096.f, g3, be3, 2);
    k_pair<<<256, 128, SM_PAIR>>>(w41, 1);
    k_wcp<<<128, 128>>>(w41);
    k_bias4<<<1, 128>>>(w41, b41);
    k_edge4<<<4032, 256, SM_E4>>>(w42, b42);
    k_stats<<<128, 256>>>(4032, 1.f / 258048.f, g4, be4, 3);
    k_foldfc<<<1, 128>>>(fcw, fcb);
    k_fc<<<BE_ * 32 / 256, 256>>>(out);
}